// round 10
// baseline (speedup 1.0000x reference)
#include <cuda_runtime.h>
#include <cuda_fp16.h>
#include <cstdint>

#define N_NODES 100000
#define N_EDGES 1600000
#define IN_F    256
#define OUT_F   256
#define D_LABEL 32
#define ALPHA   0.2f
#define EPS     1e-9f

// ---------------- scratch (device globals: allocation-free) ----------------
__device__ __half g_Wh[(size_t)N_NODES * OUT_F];    // 51.2 MB (fp16)
__device__ float  g_hA[(size_t)N_NODES * IN_F];     // 102.4 MB tf32-rounded h
__device__ float  g_hW[IN_F * OUT_F];               // 0.26 MB tf32-rounded W
__device__ uint2  g_sorted_pair[N_EDGES];           // 12.8 MB {dst, exp-bits}
__device__ int    g_count[N_NODES];
__device__ int    g_row_start[N_NODES + 1];
__device__ int    g_cursor[N_NODES];
__device__ int    g_blocksum[128];
__device__ int    g_blockoff[128];

// ---------------- streams/events, created before harness checkpoints ----------------
static cudaStream_t g_side = nullptr;
static cudaEvent_t g_ev_fork = nullptr, g_ev_join = nullptr;
namespace {
struct InitStreams {
    InitStreams() {
        cudaStreamCreateWithFlags(&g_side, cudaStreamNonBlocking);
        cudaEventCreateWithFlags(&g_ev_fork, cudaEventDisableTiming);
        cudaEventCreateWithFlags(&g_ev_join, cudaEventDisableTiming);
    }
} g_init_streams;
}

// ---------------- tf32 helpers ----------------
__device__ __forceinline__ uint32_t f2tf32(float f) {
    uint32_t r;
    asm("cvt.rna.tf32.f32 %0, %1;" : "=r"(r) : "f"(f));
    return r;
}

// elementwise tf32-round prepass (fp32 -> fp32 with low mantissa zeroed, RNA)
__global__ __launch_bounds__(256) void tf32_round_kernel(
    const float4* __restrict__ in, uint4* __restrict__ out, int n4)
{
    int i = blockIdx.x * blockDim.x + threadIdx.x;
    if (i >= n4) return;
    float4 v = in[i];
    uint4 t;
    t.x = f2tf32(v.x); t.y = f2tf32(v.y);
    t.z = f2tf32(v.z); t.w = f2tf32(v.w);
    out[i] = t;
}

// ---------------- zero count ----------------
__global__ void zero_count(int* count) {
    int i = blockIdx.x * blockDim.x + threadIdx.x;
    if (i < N_NODES) count[i] = 0;
}

// ---------------- histogram over src (4 edges/thread) ----------------
__global__ __launch_bounds__(256) void hist_kernel(
    const int* __restrict__ adj, int* __restrict__ count)
{
    int e4 = (blockIdx.x * blockDim.x + threadIdx.x) * 4;
    if (e4 >= N_EDGES) return;
    int4 s = *reinterpret_cast<const int4*>(adj + e4);
    atomicAdd(&count[s.x], 1);
    atomicAdd(&count[s.y], 1);
    atomicAdd(&count[s.z], 1);
    atomicAdd(&count[s.w], 1);
}

// ---------------- decoupled scan: 3 kernels ----------------
#define SCAN_BLK 1024
#define SCAN_NBLK ((N_NODES + SCAN_BLK - 1) / SCAN_BLK)   // 98

__global__ __launch_bounds__(SCAN_BLK) void scan_block_sums(
    const int* __restrict__ count, int* __restrict__ blocksum)
{
    __shared__ int warp_sums[32];
    int i = blockIdx.x * SCAN_BLK + threadIdx.x;
    int lane = threadIdx.x & 31, w = threadIdx.x >> 5;
    int v = (i < N_NODES) ? count[i] : 0;
    #pragma unroll
    for (int off = 16; off > 0; off >>= 1) v += __shfl_down_sync(0xffffffffu, v, off);
    if (lane == 0) warp_sums[w] = v;
    __syncthreads();
    if (w == 0) {
        int s = (lane < SCAN_BLK / 32) ? warp_sums[lane] : 0;
        #pragma unroll
        for (int off = 16; off > 0; off >>= 1) s += __shfl_down_sync(0xffffffffu, s, off);
        if (lane == 0) blocksum[blockIdx.x] = s;
    }
}

__global__ __launch_bounds__(128) void scan_offsets(
    const int* __restrict__ blocksum, int* __restrict__ blockoff)
{
    __shared__ int sh[4];
    int tid = threadIdx.x, lane = tid & 31, w = tid >> 5;
    int v = (tid < SCAN_NBLK) ? blocksum[tid] : 0;
    int x = v;
    #pragma unroll
    for (int off = 1; off < 32; off <<= 1) {
        int t = __shfl_up_sync(0xffffffffu, x, off);
        if (lane >= off) x += t;
    }
    if (lane == 31) sh[w] = x;
    __syncthreads();
    if (w == 0 && lane < 4) {
        int s = sh[lane];
        #pragma unroll
        for (int off = 1; off < 4; off <<= 1) {
            int t = __shfl_up_sync(0x0000000fu, s, off);
            if (lane >= off) s += t;
        }
        sh[lane] = s;
    }
    __syncthreads();
    int excl = x - v + (w > 0 ? sh[w - 1] : 0);
    if (tid < SCAN_NBLK) blockoff[tid] = excl;
}

__global__ __launch_bounds__(SCAN_BLK) void scan_final(
    const int* __restrict__ count, const int* __restrict__ blockoff,
    int* __restrict__ row_start, int* __restrict__ cursor)
{
    __shared__ int warp_sums[32];
    int i = blockIdx.x * SCAN_BLK + threadIdx.x;
    int lane = threadIdx.x & 31, w = threadIdx.x >> 5;
    int v = (i < N_NODES) ? count[i] : 0;
    int x = v;
    #pragma unroll
    for (int off = 1; off < 32; off <<= 1) {
        int t = __shfl_up_sync(0xffffffffu, x, off);
        if (lane >= off) x += t;
    }
    if (lane == 31) warp_sums[w] = x;
    __syncthreads();
    if (w == 0) {
        int s = warp_sums[lane];
        #pragma unroll
        for (int off = 1; off < 32; off <<= 1) {
            int t = __shfl_up_sync(0xffffffffu, s, off);
            if (lane >= off) s += t;
        }
        warp_sums[lane] = s;
    }
    __syncthreads();
    int excl = x - v + (w > 0 ? warp_sums[w - 1] : 0) + blockoff[blockIdx.x];
    if (i < N_NODES) { row_start[i] = excl; cursor[i] = excl; }
    if (i == 0) row_start[N_NODES] = N_EDGES;
}

// ---------------- mma helper (operands pre-rounded to tf32 bit patterns) ----------------
__device__ __forceinline__ void mma_tf32(float* c, const uint32_t* a, const uint32_t* b) {
    asm volatile(
        "mma.sync.aligned.m16n8k8.row.col.f32.tf32.tf32.f32 "
        "{%0,%1,%2,%3}, {%4,%5,%6,%7}, {%8,%9}, {%0,%1,%2,%3};"
        : "+f"(c[0]), "+f"(c[1]), "+f"(c[2]), "+f"(c[3])
        : "r"(a[0]), "r"(a[1]), "r"(a[2]), "r"(a[3]), "r"(b[0]), "r"(b[1]));
}

__device__ __forceinline__ void cp_async16(void* smem_dst, const void* gmem_src, int src_bytes) {
    uint32_t s = (uint32_t)__cvta_generic_to_shared(smem_dst);
    asm volatile("cp.async.cg.shared.global [%0], [%1], 16, %2;"
                 :: "r"(s), "l"(gmem_src), "r"(src_bytes));
}
#define CP_COMMIT() asm volatile("cp.async.commit_group;")
#define CP_WAIT1()  asm volatile("cp.async.wait_group 1;" ::: "memory")
#define CP_WAIT0()  asm volatile("cp.async.wait_group 0;" ::: "memory")

// ---------------- tf32 GEMM: cp.async 3-stage, fp16 output ----------------
// BM=128, BN=128, BK=16, 256 threads (8 warps, warp tile 32x64), 2 CTAs/SM.
#define GA_STRIDE 20     // As[m][k] stride (16+4)
#define GB_STRIDE 136    // Bs[k][n] stride (128+8)
#define A_STAGE (128 * GA_STRIDE)
#define B_STAGE (16 * GB_STRIDE)
#define N_STAGES 3
#define SMEM_BYTES ((N_STAGES * (A_STAGE + B_STAGE)) * 4)

__global__ __launch_bounds__(256, 2) void sgemm_tf32_kernel(
    const float* __restrict__ A,   // tf32-rounded h
    const float* __restrict__ B,   // tf32-rounded W
    __half* __restrict__ C,
    int M)
{
    extern __shared__ uint32_t smem[];
    uint32_t* AsBase = smem;
    uint32_t* BsBase = smem + N_STAGES * A_STAGE;

    const int K = 256;
    const int bx = blockIdx.x;
    const int by = blockIdx.y;
    const int tid = threadIdx.x;
    const int lane = tid & 31;
    const int wid = tid >> 5;
    const int warpM = wid >> 1;
    const int warpN = wid & 1;

    const int mBase = by * 128;
    const int nBase = bx * 128;

    const int aRow = tid >> 1;
    const int aCol = (tid & 1) * 8;
    const int gRowA0 = mBase + aRow;
    const int aBytes = (gRowA0 < M) ? 16 : 0;          // zero-fill OOB rows
    const int gRowA = (gRowA0 < M) ? gRowA0 : (M - 1); // keep address in-bounds
    const int bK = tid >> 4;
    const int bCol = (tid & 15) * 8;

    auto issue = [&](int k0, int stg) {
        uint32_t* as = AsBase + stg * A_STAGE;
        uint32_t* bs = BsBase + stg * B_STAGE;
        const float* aSrc = A + (size_t)gRowA * K + k0 + aCol;
        cp_async16(&as[aRow * GA_STRIDE + aCol], aSrc, aBytes);
        cp_async16(&as[aRow * GA_STRIDE + aCol + 4], aSrc + 4, aBytes);
        const float* bSrc = B + (size_t)(k0 + bK) * 256 + nBase + bCol;
        cp_async16(&bs[bK * GB_STRIDE + bCol], bSrc, 16);
        cp_async16(&bs[bK * GB_STRIDE + bCol + 4], bSrc + 4, 16);
        CP_COMMIT();
    };

    float c[2][8][4];
    #pragma unroll
    for (int i = 0; i < 2; i++)
        #pragma unroll
        for (int j = 0; j < 8; j++)
            #pragma unroll
            for (int l = 0; l < 4; l++) c[i][j][l] = 0.f;

    const int NIT = K / 16;   // 16
    issue(0, 0);
    issue(16, 1);

    for (int it = 0; it < NIT; it++) {
        int stg = it % N_STAGES;
        // stage `it` must be complete. For it < NIT-1 one group (it+1) may stay
        // pending; at the LAST iteration nothing was issued after group it, so
        // we must drain fully (this was the R9 race).
        if (it == NIT - 1) { CP_WAIT0(); } else { CP_WAIT1(); }
        __syncthreads();

        const uint32_t* as = AsBase + stg * A_STAGE;
        const uint32_t* bs = BsBase + stg * B_STAGE;
        #pragma unroll
        for (int kk = 0; kk < 16; kk += 8) {
            uint32_t a[2][4];
            #pragma unroll
            for (int mt = 0; mt < 2; mt++) {
                int m = warpM * 32 + mt * 16 + (lane >> 2);
                int kf = kk + (lane & 3);
                a[mt][0] = as[m * GA_STRIDE + kf];
                a[mt][1] = as[(m + 8) * GA_STRIDE + kf];
                a[mt][2] = as[m * GA_STRIDE + kf + 4];
                a[mt][3] = as[(m + 8) * GA_STRIDE + kf + 4];
            }
            uint32_t b[8][2];
            #pragma unroll
            for (int nt = 0; nt < 8; nt++) {
                int n = warpN * 64 + nt * 8 + (lane >> 2);
                int kf = kk + (lane & 3);
                b[nt][0] = bs[kf * GB_STRIDE + n];
                b[nt][1] = bs[(kf + 4) * GB_STRIDE + n];
            }
            #pragma unroll
            for (int mt = 0; mt < 2; mt++)
                #pragma unroll
                for (int nt = 0; nt < 8; nt++)
                    mma_tf32(c[mt][nt], a[mt], b[nt]);
        }
        __syncthreads();
        if (it + 2 < NIT) issue((it + 2) * 16, (it + 2) % N_STAGES);
    }

    // epilogue: fp16 stores
    #pragma unroll
    for (int mt = 0; mt < 2; mt++) {
        int m0 = mBase + warpM * 32 + mt * 16 + (lane >> 2);
        #pragma unroll
        for (int nt = 0; nt < 8; nt++) {
            int n = nBase + warpN * 64 + nt * 8 + 2 * (lane & 3);
            if (m0 < M)
                *reinterpret_cast<__half2*>(C + (size_t)m0 * 256 + n) =
                    __floats2half2_rn(c[mt][nt][0], c[mt][nt][1]);
            if (m0 + 8 < M)
                *reinterpret_cast<__half2*>(C + (size_t)(m0 + 8) * 256 + n) =
                    __floats2half2_rn(c[mt][nt][2], c[mt][nt][3]);
        }
    }
}

// ---------------- edge logits + packed CSR scatter (4 edges/thread) ----------------
__global__ __launch_bounds__(256) void logits_scatter_kernel(
    const float* __restrict__ label,
    const int* __restrict__ adj,
    int* __restrict__ cursor,
    uint2* __restrict__ sorted_pair)
{
    int e4 = (blockIdx.x * blockDim.x + threadIdx.x) * 4;
    if (e4 >= N_EDGES) return;
    int4 s4 = *reinterpret_cast<const int4*>(adj + e4);
    int4 d4 = *reinterpret_cast<const int4*>(adj + N_EDGES + e4);
    int s[4] = {s4.x, s4.y, s4.z, s4.w};
    int d[4] = {d4.x, d4.y, d4.z, d4.w};

    const float4* L = reinterpret_cast<const float4*>(label);
    float acc[4] = {0.f, 0.f, 0.f, 0.f};

    #pragma unroll
    for (int i = 0; i < D_LABEL / 4; i++) {
        float4 a[4], b[4];
        #pragma unroll
        for (int j = 0; j < 4; j++) {
            a[j] = __ldg(L + (size_t)s[j] * 8 + i);
            b[j] = __ldg(L + (size_t)d[j] * 8 + i);
        }
        #pragma unroll
        for (int j = 0; j < 4; j++)
            acc[j] += a[j].x * b[j].x + a[j].y * b[j].y + a[j].z * b[j].z + a[j].w * b[j].w;
    }

    #pragma unroll
    for (int j = 0; j < 4; j++) {
        float lr = (acc[j] >= 0.f) ? acc[j] : ALPHA * acc[j];
        float ex = __expf(lr);
        int pos = atomicAdd(&cursor[s[j]], 1);
        sorted_pair[pos] = make_uint2((unsigned)d[j], __float_as_uint(ex));
    }
}

// ---------------- aggregate: warp per node, single pass, scale at end ----------------
__global__ __launch_bounds__(256) void aggregate_kernel(
    const __half* __restrict__ Wh,
    const int* __restrict__ row_start,
    const uint2* __restrict__ sorted_pair,
    float* __restrict__ out)
{
    int gt = blockIdx.x * blockDim.x + threadIdx.x;
    int node = gt >> 5;
    int lane = gt & 31;
    if (node >= N_NODES) return;

    int start = __ldg(&row_start[node]);
    int end   = __ldg(&row_start[node + 1]);

    float acc[8];
    #pragma unroll
    for (int q = 0; q < 8; q++) acc[q] = 0.f;
    float sum = 0.f;

    const uint4* WhV = reinterpret_cast<const uint4*>(Wh);   // row stride = 32 uint4

    int j = start;
    for (; j + 3 < end; j += 4) {
        uint2 p[4]; uint4 v[4];
        #pragma unroll
        for (int u = 0; u < 4; u++) p[u] = __ldg(&sorted_pair[j + u]);
        #pragma unroll
        for (int u = 0; u < 4; u++)
            v[u] = __ldg(WhV + (size_t)p[u].x * 32 + lane);
        #pragma unroll
        for (int u = 0; u < 4; u++) {
            float a = __uint_as_float(p[u].y);
            sum += a;
            const __half2* hp = reinterpret_cast<const __half2*>(&v[u]);
            #pragma unroll
            for (int q = 0; q < 4; q++) {
                float2 f = __half22float2(hp[q]);
                acc[2 * q]     = fmaf(a, f.x, acc[2 * q]);
                acc[2 * q + 1] = fmaf(a, f.y, acc[2 * q + 1]);
            }
        }
    }
    for (; j < end; j++) {
        uint2 p = __ldg(&sorted_pair[j]);
        float a = __uint_as_float(p.y);
        sum += a;
        uint4 v = __ldg(WhV + (size_t)p.x * 32 + lane);
        const __half2* hp = reinterpret_cast<const __half2*>(&v);
        #pragma unroll
        for (int q = 0; q < 4; q++) {
            float2 f = __half22float2(hp[q]);
            acc[2 * q]     = fmaf(a, f.x, acc[2 * q]);
            acc[2 * q + 1] = fmaf(a, f.y, acc[2 * q + 1]);
        }
    }

    float inv = 1.f / fmaxf(sum, EPS);
    #pragma unroll
    for (int q = 0; q < 8; q++) acc[q] *= inv;

    float4* out4 = reinterpret_cast<float4*>(out + (size_t)node * 256 + lane * 8);
    out4[0] = make_float4(acc[0], acc[1], acc[2], acc[3]);
    out4[1] = make_float4(acc[4], acc[5], acc[6], acc[7]);
}

// ---------------- launch ----------------
extern "C" void kernel_launch(void* const* d_in, const int* in_sizes, int n_in,
                              void* d_out, int out_size) {
    const float* h      = (const float*)d_in[0];   // [N, 256]
    const float* label  = (const float*)d_in[1];   // [N, 32]
    const float* W      = (const float*)d_in[2];   // [256, 256]
    const int*   adj    = (const int*)d_in[3];     // [2, E] int32
    float* out = (float*)d_out;                    // [N, 256]

    __half* Wh;
    float *hA, *hW;
    uint2* sorted_pair;
    int *count, *row_start, *cursor, *blocksum, *blockoff;
    cudaGetSymbolAddress((void**)&Wh, g_Wh);
    cudaGetSymbolAddress((void**)&hA, g_hA);
    cudaGetSymbolAddress((void**)&hW, g_hW);
    cudaGetSymbolAddress((void**)&sorted_pair, g_sorted_pair);
    cudaGetSymbolAddress((void**)&count, g_count);
    cudaGetSymbolAddress((void**)&row_start, g_row_start);
    cudaGetSymbolAddress((void**)&cursor, g_cursor);
    cudaGetSymbolAddress((void**)&blocksum, g_blocksum);
    cudaGetSymbolAddress((void**)&blockoff, g_blockoff);

    static bool attr_set = false;
    if (!attr_set) {
        cudaFuncSetAttribute(sgemm_tf32_kernel,
                             cudaFuncAttributeMaxDynamicSharedMemorySize, SMEM_BYTES);
        attr_set = true;
    }

    // fork: tf32 pre-round + GEMM on side stream, overlapped with label/CSR chain
    cudaEventRecord(g_ev_fork, 0);
    cudaStreamWaitEvent(g_side, g_ev_fork, 0);
    {
        int n4h = N_NODES * IN_F / 4;
        tf32_round_kernel<<<(n4h + 255) / 256, 256, 0, g_side>>>(
            (const float4*)h, (uint4*)hA, n4h);
        int n4w = IN_F * OUT_F / 4;
        tf32_round_kernel<<<(n4w + 255) / 256, 256, 0, g_side>>>(
            (const float4*)W, (uint4*)hW, n4w);
        dim3 grid(OUT_F / 128, (N_NODES + 127) / 128);
        sgemm_tf32_kernel<<<grid, 256, SMEM_BYTES, g_side>>>(hA, hW, Wh, N_NODES);
    }
    cudaEventRecord(g_ev_join, g_side);

    // main chain (default stream)
    zero_count<<<(N_NODES + 255) / 256, 256>>>(count);
    hist_kernel<<<(N_EDGES / 4 + 255) / 256, 256>>>(adj, count);
    scan_block_sums<<<SCAN_NBLK, SCAN_BLK>>>(count, blocksum);
    scan_offsets<<<1, 128>>>(blocksum, blockoff);
    scan_final<<<SCAN_NBLK, SCAN_BLK>>>(count, blockoff, row_start, cursor);
    logits_scatter_kernel<<<(N_EDGES / 4 + 255) / 256, 256>>>(
        label, adj, cursor, sorted_pair);

    // join: aggregate needs both Wh and the CSR arrays
    cudaStreamWaitEvent(0, g_ev_join, 0);
    {
        long long threads = (long long)N_NODES * 32;
        int blocks = (int)((threads + 255) / 256);
        aggregate_kernel<<<blocks, 256>>>(Wh, row_start, sorted_pair, out);
    }
}

// round 14
// speedup vs baseline: 1.0729x; 1.0729x over previous
#include <cuda_runtime.h>
#include <cuda_fp16.h>
#include <cstdint>

#define N_NODES 100000
#define N_EDGES 1600000
#define IN_F    256
#define OUT_F   256
#define D_LABEL 32
#define ALPHA   0.2f
#define EPS     1e-9f

// ---------------- scratch (device globals: allocation-free) ----------------
__device__ __half g_Wh[(size_t)N_NODES * OUT_F];    // 51.2 MB (fp16)
__device__ float  g_hW[IN_F * OUT_F];               // 0.26 MB tf32-rounded W
__device__ uint2  g_sorted_pair[N_EDGES];           // 12.8 MB {dst, exp-bits}
__device__ int    g_count[N_NODES];
__device__ int    g_row_start[N_NODES + 1];
__device__ int    g_cursor[N_NODES];
__device__ int    g_blocksum[128];
__device__ int    g_blockoff[128];

// ---------------- streams/events, created before harness checkpoints ----------------
static cudaStream_t g_side = nullptr;
static cudaEvent_t g_ev_fork = nullptr, g_ev_join = nullptr;
namespace {
struct InitStreams {
    InitStreams() {
        cudaStreamCreateWithFlags(&g_side, cudaStreamNonBlocking);
        cudaEventCreateWithFlags(&g_ev_fork, cudaEventDisableTiming);
        cudaEventCreateWithFlags(&g_ev_join, cudaEventDisableTiming);
    }
} g_init_streams;
}

// ---------------- tf32 helpers ----------------
__device__ __forceinline__ uint32_t f2tf32(float f) {
    uint32_t r;
    asm("cvt.rna.tf32.f32 %0, %1;" : "=r"(r) : "f"(f));
    return r;
}

// elementwise tf32-round prepass (W only: 64K elements)
__global__ __launch_bounds__(256) void tf32_round_kernel(
    const float4* __restrict__ in, uint4* __restrict__ out, int n4)
{
    int i = blockIdx.x * blockDim.x + threadIdx.x;
    if (i >= n4) return;
    float4 v = in[i];
    uint4 t;
    t.x = f2tf32(v.x); t.y = f2tf32(v.y);
    t.z = f2tf32(v.z); t.w = f2tf32(v.w);
    out[i] = t;
}

// ---------------- histogram over src (4 edges/thread) ----------------
__global__ __launch_bounds__(256) void hist_kernel(
    const int* __restrict__ adj, int* __restrict__ count)
{
    int e4 = (blockIdx.x * blockDim.x + threadIdx.x) * 4;
    if (e4 >= N_EDGES) return;
    int4 s = *reinterpret_cast<const int4*>(adj + e4);
    atomicAdd(&count[s.x], 1);
    atomicAdd(&count[s.y], 1);
    atomicAdd(&count[s.z], 1);
    atomicAdd(&count[s.w], 1);
}

// ---------------- decoupled scan: 3 kernels ----------------
#define SCAN_BLK 1024
#define SCAN_NBLK ((N_NODES + SCAN_BLK - 1) / SCAN_BLK)   // 98

__global__ __launch_bounds__(SCAN_BLK) void scan_block_sums(
    const int* __restrict__ count, int* __restrict__ blocksum)
{
    __shared__ int warp_sums[32];
    int i = blockIdx.x * SCAN_BLK + threadIdx.x;
    int lane = threadIdx.x & 31, w = threadIdx.x >> 5;
    int v = (i < N_NODES) ? count[i] : 0;
    #pragma unroll
    for (int off = 16; off > 0; off >>= 1) v += __shfl_down_sync(0xffffffffu, v, off);
    if (lane == 0) warp_sums[w] = v;
    __syncthreads();
    if (w == 0) {
        int s = (lane < SCAN_BLK / 32) ? warp_sums[lane] : 0;
        #pragma unroll
        for (int off = 16; off > 0; off >>= 1) s += __shfl_down_sync(0xffffffffu, s, off);
        if (lane == 0) blocksum[blockIdx.x] = s;
    }
}

__global__ __launch_bounds__(128) void scan_offsets(
    const int* __restrict__ blocksum, int* __restrict__ blockoff)
{
    __shared__ int sh[4];
    int tid = threadIdx.x, lane = tid & 31, w = tid >> 5;
    int v = (tid < SCAN_NBLK) ? blocksum[tid] : 0;
    int x = v;
    #pragma unroll
    for (int off = 1; off < 32; off <<= 1) {
        int t = __shfl_up_sync(0xffffffffu, x, off);
        if (lane >= off) x += t;
    }
    if (lane == 31) sh[w] = x;
    __syncthreads();
    if (w == 0 && lane < 4) {
        int s = sh[lane];
        #pragma unroll
        for (int off = 1; off < 4; off <<= 1) {
            int t = __shfl_up_sync(0x0000000fu, s, off);
            if (lane >= off) s += t;
        }
        sh[lane] = s;
    }
    __syncthreads();
    int excl = x - v + (w > 0 ? sh[w - 1] : 0);
    if (tid < SCAN_NBLK) blockoff[tid] = excl;
}

__global__ __launch_bounds__(SCAN_BLK) void scan_final(
    const int* __restrict__ count, const int* __restrict__ blockoff,
    int* __restrict__ row_start, int* __restrict__ cursor)
{
    __shared__ int warp_sums[32];
    int i = blockIdx.x * SCAN_BLK + threadIdx.x;
    int lane = threadIdx.x & 31, w = threadIdx.x >> 5;
    int v = (i < N_NODES) ? count[i] : 0;
    int x = v;
    #pragma unroll
    for (int off = 1; off < 32; off <<= 1) {
        int t = __shfl_up_sync(0xffffffffu, x, off);
        if (lane >= off) x += t;
    }
    if (lane == 31) warp_sums[w] = x;
    __syncthreads();
    if (w == 0) {
        int s = warp_sums[lane];
        #pragma unroll
        for (int off = 1; off < 32; off <<= 1) {
            int t = __shfl_up_sync(0xffffffffu, s, off);
            if (lane >= off) s += t;
        }
        warp_sums[lane] = s;
    }
    __syncthreads();
    int excl = x - v + (w > 0 ? warp_sums[w - 1] : 0) + blockoff[blockIdx.x];
    if (i < N_NODES) { row_start[i] = excl; cursor[i] = excl; }
    if (i == 0) row_start[N_NODES] = N_EDGES;
}

// ---------------- mma helper ----------------
__device__ __forceinline__ void mma_tf32(float* c, const uint32_t* a, const uint32_t* b) {
    asm volatile(
        "mma.sync.aligned.m16n8k8.row.col.f32.tf32.tf32.f32 "
        "{%0,%1,%2,%3}, {%4,%5,%6,%7}, {%8,%9}, {%0,%1,%2,%3};"
        : "+f"(c[0]), "+f"(c[1]), "+f"(c[2]), "+f"(c[3])
        : "r"(a[0]), "r"(a[1]), "r"(a[2]), "r"(a[3]), "r"(b[0]), "r"(b[1]));
}

__device__ __forceinline__ void cp_async16(void* smem_dst, const void* gmem_src, int src_bytes) {
    uint32_t s = (uint32_t)__cvta_generic_to_shared(smem_dst);
    asm volatile("cp.async.cg.shared.global [%0], [%1], 16, %2;"
                 :: "r"(s), "l"(gmem_src), "r"(src_bytes));
}
#define CP_COMMIT() asm volatile("cp.async.commit_group;")
#define CP_WAIT1()  asm volatile("cp.async.wait_group 1;" ::: "memory")
#define CP_WAIT0()  asm volatile("cp.async.wait_group 0;" ::: "memory")

// ---------------- tf32 GEMM: cp.async 3-stage ----------------
// A raw fp32 (RNA cvt applied at fragment load); B pre-rounded in gmem.
// BM=128, BN=128, BK=16, 256 threads (8 warps, warp tile 32x64), 2 CTAs/SM.
#define GA_STRIDE 20     // As[m][k] stride (16+4)
#define GB_STRIDE 136    // Bs[k][n] stride (128+8)
#define A_STAGE (128 * GA_STRIDE)
#define B_STAGE (16 * GB_STRIDE)
#define N_STAGES 3
#define SMEM_BYTES ((N_STAGES * (A_STAGE + B_STAGE)) * 4)

__global__ __launch_bounds__(256, 2) void sgemm_tf32_kernel(
    const float* __restrict__ A,   // raw h
    const float* __restrict__ B,   // tf32-rounded W
    __half* __restrict__ C,
    int M)
{
    extern __shared__ uint32_t smem[];
    uint32_t* AsBase = smem;
    uint32_t* BsBase = smem + N_STAGES * A_STAGE;

    const int K = 256;
    const int bx = blockIdx.x;
    const int by = blockIdx.y;
    const int tid = threadIdx.x;
    const int lane = tid & 31;
    const int wid = tid >> 5;
    const int warpM = wid >> 1;
    const int warpN = wid & 1;

    const int mBase = by * 128;
    const int nBase = bx * 128;

    const int aRow = tid >> 1;
    const int aCol = (tid & 1) * 8;
    const int gRowA0 = mBase + aRow;
    const int aBytes = (gRowA0 < M) ? 16 : 0;          // zero-fill OOB rows
    const int gRowA = (gRowA0 < M) ? gRowA0 : (M - 1); // keep address in-bounds
    const int bK = tid >> 4;
    const int bCol = (tid & 15) * 8;

    auto issue = [&](int k0, int stg) {
        uint32_t* as = AsBase + stg * A_STAGE;
        uint32_t* bs = BsBase + stg * B_STAGE;
        const float* aSrc = A + (size_t)gRowA * K + k0 + aCol;
        cp_async16(&as[aRow * GA_STRIDE + aCol], aSrc, aBytes);
        cp_async16(&as[aRow * GA_STRIDE + aCol + 4], aSrc + 4, aBytes);
        const float* bSrc = B + (size_t)(k0 + bK) * 256 + nBase + bCol;
        cp_async16(&bs[bK * GB_STRIDE + bCol], bSrc, 16);
        cp_async16(&bs[bK * GB_STRIDE + bCol + 4], bSrc + 4, 16);
        CP_COMMIT();
    };

    float c[2][8][4];
    #pragma unroll
    for (int i = 0; i < 2; i++)
        #pragma unroll
        for (int j = 0; j < 8; j++)
            #pragma unroll
            for (int l = 0; l < 4; l++) c[i][j][l] = 0.f;

    const int NIT = K / 16;   // 16
    issue(0, 0);
    issue(16, 1);

    for (int it = 0; it < NIT; it++) {
        int stg = it % N_STAGES;
        // stage `it` must be complete; at the last iteration nothing was issued
        // after group `it`, so drain fully (R9's race).
        if (it == NIT - 1) { CP_WAIT0(); } else { CP_WAIT1(); }
        __syncthreads();

        const uint32_t* as = AsBase + stg * A_STAGE;
        const uint32_t* bs = BsBase + stg * B_STAGE;
        #pragma unroll
        for (int kk = 0; kk < 16; kk += 8) {
            uint32_t a[2][4];
            #pragma unroll
            for (int mt = 0; mt < 2; mt++) {
                int m = warpM * 32 + mt * 16 + (lane >> 2);
                int kf = kk + (lane & 3);
                // A fragments carry raw fp32; round to tf32 (RNA) here.
                a[mt][0] = f2tf32(__uint_as_float(as[m * GA_STRIDE + kf]));
                a[mt][1] = f2tf32(__uint_as_float(as[(m + 8) * GA_STRIDE + kf]));
                a[mt][2] = f2tf32(__uint_as_float(as[m * GA_STRIDE + kf + 4]));
                a[mt][3] = f2tf32(__uint_as_float(as[(m + 8) * GA_STRIDE + kf + 4]));
            }
            uint32_t b[8][2];
            #pragma unroll
            for (int nt = 0; nt < 8; nt++) {
                int n = warpN * 64 + nt * 8 + (lane >> 2);
                int kf = kk + (lane & 3);
                b[nt][0] = bs[kf * GB_STRIDE + n];
                b[nt][1] = bs[(kf + 4) * GB_STRIDE + n];
            }
            #pragma unroll
            for (int mt = 0; mt < 2; mt++)
                #pragma unroll
                for (int nt = 0; nt < 8; nt++)
                    mma_tf32(c[mt][nt], a[mt], b[nt]);
        }
        __syncthreads();
        if (it + 2 < NIT) issue((it + 2) * 16, (it + 2) % N_STAGES);
    }

    // epilogue: fp16 stores
    #pragma unroll
    for (int mt = 0; mt < 2; mt++) {
        int m0 = mBase + warpM * 32 + mt * 16 + (lane >> 2);
        #pragma unroll
        for (int nt = 0; nt < 8; nt++) {
            int n = nBase + warpN * 64 + nt * 8 + 2 * (lane & 3);
            if (m0 < M)
                *reinterpret_cast<__half2*>(C + (size_t)m0 * 256 + n) =
                    __floats2half2_rn(c[mt][nt][0], c[mt][nt][1]);
            if (m0 + 8 < M)
                *reinterpret_cast<__half2*>(C + (size_t)(m0 + 8) * 256 + n) =
                    __floats2half2_rn(c[mt][nt][2], c[mt][nt][3]);
        }
    }
}

// ---------------- edge logits + packed CSR scatter (4 edges/thread) ----------------
__global__ __launch_bounds__(256) void logits_scatter_kernel(
    const float* __restrict__ label,
    const int* __restrict__ adj,
    int* __restrict__ cursor,
    uint2* __restrict__ sorted_pair)
{
    int e4 = (blockIdx.x * blockDim.x + threadIdx.x) * 4;
    if (e4 >= N_EDGES) return;
    int4 s4 = *reinterpret_cast<const int4*>(adj + e4);
    int4 d4 = *reinterpret_cast<const int4*>(adj + N_EDGES + e4);
    int s[4] = {s4.x, s4.y, s4.z, s4.w};
    int d[4] = {d4.x, d4.y, d4.z, d4.w};

    const float4* L = reinterpret_cast<const float4*>(label);
    float acc[4] = {0.f, 0.f, 0.f, 0.f};

    #pragma unroll
    for (int i = 0; i < D_LABEL / 4; i++) {
        float4 a[4], b[4];
        #pragma unroll
        for (int j = 0; j < 4; j++) {
            a[j] = __ldg(L + (size_t)s[j] * 8 + i);
            b[j] = __ldg(L + (size_t)d[j] * 8 + i);
        }
        #pragma unroll
        for (int j = 0; j < 4; j++)
            acc[j] += a[j].x * b[j].x + a[j].y * b[j].y + a[j].z * b[j].z + a[j].w * b[j].w;
    }

    #pragma unroll
    for (int j = 0; j < 4; j++) {
        float lr = (acc[j] >= 0.f) ? acc[j] : ALPHA * acc[j];
        float ex = __expf(lr);
        int pos = atomicAdd(&cursor[s[j]], 1);
        sorted_pair[pos] = make_uint2((unsigned)d[j], __float_as_uint(ex));
    }
}

// ---------------- aggregate: warp per node, single pass, scale at end ----------------
__global__ __launch_bounds__(256) void aggregate_kernel(
    const __half* __restrict__ Wh,
    const int* __restrict__ row_start,
    const uint2* __restrict__ sorted_pair,
    float* __restrict__ out)
{
    int gt = blockIdx.x * blockDim.x + threadIdx.x;
    int node = gt >> 5;
    int lane = gt & 31;
    if (node >= N_NODES) return;

    int start = __ldg(&row_start[node]);
    int end   = __ldg(&row_start[node + 1]);

    float acc[8];
    #pragma unroll
    for (int q = 0; q < 8; q++) acc[q] = 0.f;
    float sum = 0.f;

    const uint4* WhV = reinterpret_cast<const uint4*>(Wh);   // row stride = 32 uint4

    int j = start;
    for (; j + 3 < end; j += 4) {
        uint2 p[4]; uint4 v[4];
        #pragma unroll
        for (int u = 0; u < 4; u++) p[u] = __ldg(&sorted_pair[j + u]);
        #pragma unroll
        for (int u = 0; u < 4; u++)
            v[u] = __ldg(WhV + (size_t)p[u].x * 32 + lane);
        #pragma unroll
        for (int u = 0; u < 4; u++) {
            float a = __uint_as_float(p[u].y);
            sum += a;
            const __half2* hp = reinterpret_cast<const __half2*>(&v[u]);
            #pragma unroll
            for (int q = 0; q < 4; q++) {
                float2 f = __half22float2(hp[q]);
                acc[2 * q]     = fmaf(a, f.x, acc[2 * q]);
                acc[2 * q + 1] = fmaf(a, f.y, acc[2 * q + 1]);
            }
        }
    }
    for (; j < end; j++) {
        uint2 p = __ldg(&sorted_pair[j]);
        float a = __uint_as_float(p.y);
        sum += a;
        uint4 v = __ldg(WhV + (size_t)p.x * 32 + lane);
        const __half2* hp = reinterpret_cast<const __half2*>(&v);
        #pragma unroll
        for (int q = 0; q < 4; q++) {
            float2 f = __half22float2(hp[q]);
            acc[2 * q]     = fmaf(a, f.x, acc[2 * q]);
            acc[2 * q + 1] = fmaf(a, f.y, acc[2 * q + 1]);
        }
    }

    float inv = 1.f / fmaxf(sum, EPS);
    #pragma unroll
    for (int q = 0; q < 8; q++) acc[q] *= inv;

    float4* out4 = reinterpret_cast<float4*>(out + (size_t)node * 256 + lane * 8);
    out4[0] = make_float4(acc[0], acc[1], acc[2], acc[3]);
    out4[1] = make_float4(acc[4], acc[5], acc[6], acc[7]);
}

// ---------------- launch ----------------
extern "C" void kernel_launch(void* const* d_in, const int* in_sizes, int n_in,
                              void* d_out, int out_size) {
    const float* h      = (const float*)d_in[0];   // [N, 256]
    const float* label  = (const float*)d_in[1];   // [N, 32]
    const float* W      = (const float*)d_in[2];   // [256, 256]
    const int*   adj    = (const int*)d_in[3];     // [2, E] int32
    float* out = (float*)d_out;                    // [N, 256]

    __half* Wh;
    float* hW;
    uint2* sorted_pair;
    int *count, *row_start, *cursor, *blocksum, *blockoff;
    cudaGetSymbolAddress((void**)&Wh, g_Wh);
    cudaGetSymbolAddress((void**)&hW, g_hW);
    cudaGetSymbolAddress((void**)&sorted_pair, g_sorted_pair);
    cudaGetSymbolAddress((void**)&count, g_count);
    cudaGetSymbolAddress((void**)&row_start, g_row_start);
    cudaGetSymbolAddress((void**)&cursor, g_cursor);
    cudaGetSymbolAddress((void**)&blocksum, g_blocksum);
    cudaGetSymbolAddress((void**)&blockoff, g_blockoff);

    static bool attr_set = false;
    if (!attr_set) {
        cudaFuncSetAttribute(sgemm_tf32_kernel,
                             cudaFuncAttributeMaxDynamicSharedMemorySize, SMEM_BYTES);
        attr_set = true;
    }

    // fork: round W (tiny) + GEMM on side stream
    cudaEventRecord(g_ev_fork, 0);
    cudaStreamWaitEvent(g_side, g_ev_fork, 0);
    {
        int n4w = IN_F * OUT_F / 4;
        tf32_round_kernel<<<(n4w + 255) / 256, 256, 0, g_side>>>(
            (const float4*)W, (uint4*)hW, n4w);
        dim3 grid(OUT_F / 128, (N_NODES + 127) / 128);
        sgemm_tf32_kernel<<<grid, 256, SMEM_BYTES, g_side>>>(h, hW, Wh, N_NODES);
    }
    cudaEventRecord(g_ev_join, g_side);

    // main chain (default stream)
    cudaMemsetAsync(count, 0, N_NODES * sizeof(int), 0);
    hist_kernel<<<(N_EDGES / 4 + 255) / 256, 256>>>(adj, count);
    scan_block_sums<<<SCAN_NBLK, SCAN_BLK>>>(count, blocksum);
    scan_offsets<<<1, 128>>>(blocksum, blockoff);
    scan_final<<<SCAN_NBLK, SCAN_BLK>>>(count, blockoff, row_start, cursor);
    logits_scatter_kernel<<<(N_EDGES / 4 + 255) / 256, 256>>>(
        label, adj, cursor, sorted_pair);

    // join: aggregate needs both Wh and the CSR arrays
    cudaStreamWaitEvent(0, g_ev_join, 0);
    {
        long long threads = (long long)N_NODES * 32;
        int blocks = (int)((threads + 255) / 256);
        aggregate_kernel<<<blocks, 256>>>(Wh, row_start, sorted_pair, out);
    }
}